// round 2
// baseline (speedup 1.0000x reference)
#include <cuda_runtime.h>
#include <math.h>

// Problem constants (fixed by reference setup)
#define Bsz 2
#define Dm  128
#define Nn  2048
#define Hh  4
#define DH  32

// ---------------- scratch (device globals; no allocation) ----------------
__device__ float g_x0[Bsz*Dm*Nn];
__device__ float g_x1[Bsz*Dm*Nn];
__device__ float g_s0[Bsz*Dm*Nn];
__device__ float g_s1[Bsz*Dm*Nn];
__device__ float g_q [Bsz*Dm*Nn];
__device__ float g_k [Bsz*Dm*Nn];
__device__ float g_v [Bsz*Dm*Nn];
__device__ float g_prob[(size_t)Bsz*Hh*Nn*Nn];   // 134 MB, layer-0 worst case
__device__ float g_msg[Bsz*Dm*Nn];
__device__ float g_y [Bsz*2*Dm*Nn];
__device__ float g_h [Bsz*2*Dm*Nn];
__device__ float g_p0[Bsz*Nn];
__device__ float g_p1[Bsz*Nn];
__device__ int   g_idx0[Bsz*Nn];
__device__ int   g_idx1[Bsz*Nn];

// ---------------- tiny utility kernels ----------------
__global__ void copyf_kernel(const float* __restrict__ src, float* __restrict__ dst, int n)
{
    int g = blockIdx.x*256 + threadIdx.x;
    if (g < n) dst[g] = src[g];
}

__global__ void zero_kernel(float* __restrict__ p, int n)
{
    int g = blockIdx.x*256 + threadIdx.x;
    if (g < n) p[g] = 0.0f;
}

__global__ void iota_kernel(int* __restrict__ idx)
{
    int g = blockIdx.x*256 + threadIdx.x;   // over Bsz*Nn
    if (g < Bsz*Nn) idx[g] = g % Nn;
}

__global__ void out_kernel(const float* __restrict__ x0, const float* __restrict__ x1,
                           float* __restrict__ out)
{
    int g = blockIdx.x*256 + threadIdx.x;   // over Bsz*Dm*Nn
    if (g < Bsz*Dm*Nn) {
        out[g] = x0[g];
        out[g + Bsz*Dm*Nn] = x1[g];
    }
}

// copy x into first 128 channels of y ([B,256,N])
__global__ void copy_xy_kernel(const float* __restrict__ x, float* __restrict__ y)
{
    int g = blockIdx.x*256 + threadIdx.x;   // over Bsz*Dm*Nn
    if (g >= Bsz*Dm*Nn) return;
    int b = g / (Dm*Nn);
    int r = g - b*(Dm*Nn);
    y[(size_t)b*2*Dm*Nn + r] = x[g];
}

// ---------------- gather: s[b,d,k] = x[b,d,idx[b,k]] ----------------
__global__ void gather_kernel(const float* __restrict__ x, const int* __restrict__ idx,
                              float* __restrict__ s, int K)
{
    int g = blockIdx.x*256 + threadIdx.x;
    int total = Bsz*Dm*K;
    if (g >= total) return;
    int b = g / (Dm*K);
    int r = g - b*(Dm*K);
    int d = r / K, kk = r - d*K;
    s[g] = x[(size_t)b*Dm*Nn + (size_t)d*Nn + idx[b*Nn + kk]];
}

// ---------------- pointwise conv GEMM: Y[b,o,n] = sum_i W[o,i] X[b,i,n] + bias[o] ----------------
// grid: (Ncols/64, Co/64, B), block 256. BM=BN=64, BK=16, 4x4 microtile.
__global__ void pw_gemm_kernel(const float* __restrict__ W, const float* __restrict__ bias,
                               const float* __restrict__ X, int xbStride,
                               float* __restrict__ Y, int ybStride,
                               int Ci, int Ncols, int accumulate)
{
    __shared__ float Ws[64][17];
    __shared__ float Xs[16][64];
    int b = blockIdx.z;
    const float* Xb = X + (size_t)b * xbStride;
    float*       Yb = Y + (size_t)b * ybStride;
    int coTile  = blockIdx.y * 64;
    int colTile = blockIdx.x * 64;
    int tid = threadIdx.x;
    int ty = tid >> 4, tx = tid & 15;
    float acc[4][4] = {};

    for (int kt = 0; kt < Ci; kt += 16) {
        #pragma unroll
        for (int q = 0; q < 4; q++) {
            int e = tid + 256*q;
            int r = e >> 4, c = e & 15;
            Ws[r][c] = W[(size_t)(coTile + r)*Ci + kt + c];
        }
        #pragma unroll
        for (int q = 0; q < 4; q++) {
            int e = tid + 256*q;
            int r = e >> 6, c = e & 63;
            Xs[r][c] = Xb[(size_t)(kt + r)*Ncols + colTile + c];
        }
        __syncthreads();
        #pragma unroll
        for (int kk = 0; kk < 16; kk++) {
            float a[4], bb[4];
            #pragma unroll
            for (int i = 0; i < 4; i++) a[i]  = Ws[ty*4+i][kk];
            #pragma unroll
            for (int j = 0; j < 4; j++) bb[j] = Xs[kk][tx*4+j];
            #pragma unroll
            for (int i = 0; i < 4; i++)
                #pragma unroll
                for (int j = 0; j < 4; j++)
                    acc[i][j] += a[i]*bb[j];
        }
        __syncthreads();
    }

    #pragma unroll
    for (int i = 0; i < 4; i++) {
        int row = coTile + ty*4 + i;
        float bi = bias[row];
        #pragma unroll
        for (int j = 0; j < 4; j++) {
            int col = colTile + tx*4 + j;
            size_t off = (size_t)row*Ncols + col;
            float val = acc[i][j] + bi;
            Yb[off] = accumulate ? (Yb[off] + val) : val;
        }
    }
}

// ---------------- scores: prob[b,h,n,k] = scale * sum_i q[b,i*4+h,n]*kb[b,i*4+h,k] ----------------
// grid: (K/64, N/64, B*H), block 256
__global__ void scores_kernel(const float* __restrict__ q, const float* __restrict__ kbuf,
                              float* __restrict__ prob, int K)
{
    __shared__ float Qs[32][64];
    __shared__ float Ks[32][64];
    int z = blockIdx.z; int b = z >> 2; int h = z & 3;
    int nTile = blockIdx.y * 64;
    int kTile = blockIdx.x * 64;
    int tid = threadIdx.x; int ty = tid >> 4, tx = tid & 15;
    const float* qb = q    + (size_t)b*Dm*Nn;
    const float* kb = kbuf + (size_t)b*Dm*K;

    #pragma unroll
    for (int qq = 0; qq < 8; qq++) {
        int e = tid + 256*qq;
        int i = e >> 6, c = e & 63;
        Qs[i][c] = qb[(size_t)(i*4 + h)*Nn + nTile + c];
        Ks[i][c] = kb[(size_t)(i*4 + h)*K  + kTile + c];
    }
    __syncthreads();

    float acc[4][4] = {};
    #pragma unroll
    for (int i = 0; i < 32; i++) {
        float a[4], c4[4];
        #pragma unroll
        for (int r = 0; r < 4; r++) a[r]  = Qs[i][ty*4+r];
        #pragma unroll
        for (int j = 0; j < 4; j++) c4[j] = Ks[i][tx*4+j];
        #pragma unroll
        for (int r = 0; r < 4; r++)
            #pragma unroll
            for (int j = 0; j < 4; j++)
                acc[r][j] += a[r]*c4[j];
    }

    const float scale = 0.17677669529663687f;   // 1/sqrt(32)
    float* pr = prob + (size_t)z*Nn*K;
    #pragma unroll
    for (int r = 0; r < 4; r++)
        #pragma unroll
        for (int j = 0; j < 4; j++)
            pr[(size_t)(nTile + ty*4 + r)*K + kTile + tx*4 + j] = acc[r][j]*scale;
}

// ---------------- softmax over K (one block per row; K in {256,512,1024,2048}) ----------------
__global__ void softmax_kernel(float* __restrict__ prob, int K)
{
    float* p = prob + (size_t)blockIdx.x * K;
    int tid = threadIdx.x;
    int cnt = K >> 8;
    float v[8];
    float m = -1e30f;
    for (int j = 0; j < cnt; j++) { v[j] = p[tid + j*256]; m = fmaxf(m, v[j]); }
    __shared__ float red[256];
    red[tid] = m; __syncthreads();
    for (int s = 128; s > 0; s >>= 1) { if (tid < s) red[tid] = fmaxf(red[tid], red[tid+s]); __syncthreads(); }
    m = red[0]; __syncthreads();
    float sum = 0.0f;
    for (int j = 0; j < cnt; j++) { v[j] = expf(v[j] - m); sum += v[j]; }
    red[tid] = sum; __syncthreads();
    for (int s = 128; s > 0; s >>= 1) { if (tid < s) red[tid] += red[tid+s]; __syncthreads(); }
    float inv = 1.0f / red[0];
    for (int j = 0; j < cnt; j++) p[tid + j*256] = v[j]*inv;
}

// ---------------- key importance: p[b,k] = (1/H) sum_{h,n} prob[b,h,n,k] ----------------
// grid: ((B*K+255)/256, Nn/128), block 256; pout must be zeroed first.
__global__ void pred_kernel(const float* __restrict__ prob, float* __restrict__ pout, int K)
{
    int g = blockIdx.x*256 + threadIdx.x;
    if (g >= Bsz*K) return;
    int b = g / K, k = g - b*K;
    int n0 = blockIdx.y * 128;
    const float* base = prob + (size_t)b*Hh*Nn*K + k;
    float s = 0.0f;
    for (int h = 0; h < Hh; h++) {
        const float* ph = base + ((size_t)h*Nn + n0)*K;
        #pragma unroll 4
        for (int n = 0; n < 128; n++) s += ph[(size_t)n*K];
    }
    atomicAdd(&pout[g], s * 0.25f);
}

// ---------------- msg: msg[b,i*4+h,n] = sum_k prob[b,h,n,k]*v[b,i*4+h,k] ----------------
// grid: (N/64, B*H), block 256
__global__ void msg_kernel(const float* __restrict__ prob, const float* __restrict__ v,
                           float* __restrict__ msg, int K)
{
    __shared__ float Vs[32][65];
    __shared__ float Ps[64][65];
    int z = blockIdx.y; int b = z >> 2, h = z & 3;
    int nTile = blockIdx.x * 64;
    int tid = threadIdx.x;
    const float* vb = v    + (size_t)b*Dm*K;
    const float* pr = prob + (size_t)z*Nn*K;
    int i = tid & 31, ng = tid >> 5;
    float acc[8] = {};

    for (int kt = 0; kt < K; kt += 64) {
        #pragma unroll
        for (int qq = 0; qq < 8; qq++) {
            int e = tid + 256*qq;
            int r = e >> 6, c = e & 63;
            Vs[r][c] = vb[(size_t)(r*4 + h)*K + kt + c];
        }
        #pragma unroll
        for (int qq = 0; qq < 16; qq++) {
            int e = tid + 256*qq;
            int r = e >> 6, c = e & 63;
            Ps[r][c] = pr[(size_t)(nTile + r)*K + kt + c];
        }
        __syncthreads();
        #pragma unroll
        for (int kk = 0; kk < 64; kk++) {
            float vv = Vs[i][kk];
            #pragma unroll
            for (int j = 0; j < 8; j++) acc[j] += vv * Ps[ng*8 + j][kk];
        }
        __syncthreads();
    }

    float* mb = msg + (size_t)b*Dm*Nn + (size_t)(i*4 + h)*Nn + nTile + ng*8;
    #pragma unroll
    for (int j = 0; j < 8; j++) mb[j] = acc[j];
}

// ---------------- instance norm (eps=1e-3) + relu, in place; one block per (b,c) row ----------------
__global__ void instnorm_relu_kernel(float* __restrict__ x)
{
    float* p = x + (size_t)blockIdx.x * Nn;
    int tid = threadIdx.x;
    float v[8];
    float s = 0.0f;
    #pragma unroll
    for (int j = 0; j < 8; j++) { v[j] = p[tid + j*256]; s += v[j]; }
    __shared__ float red[256];
    red[tid] = s; __syncthreads();
    for (int st = 128; st > 0; st >>= 1) { if (tid < st) red[tid] += red[tid+st]; __syncthreads(); }
    float mean = red[0] * (1.0f/Nn);
    __syncthreads();
    float s2 = 0.0f;
    #pragma unroll
    for (int j = 0; j < 8; j++) { float d = v[j] - mean; s2 += d*d; }
    red[tid] = s2; __syncthreads();
    for (int st = 128; st > 0; st >>= 1) { if (tid < st) red[tid] += red[tid+st]; __syncthreads(); }
    float rs = rsqrtf(red[0]*(1.0f/Nn) + 1e-3f);
    #pragma unroll
    for (int j = 0; j < 8; j++) {
        float o = (v[j] - mean)*rs;
        p[tid + j*256] = o > 0.0f ? o : 0.0f;
    }
}

// ---------------- pooling: exact top-k (jax.lax.top_k tie-break) + sorted gather ----------------
// one block per batch; idx updated in place (values staged in shared first)
__global__ void pool_kernel(const float* __restrict__ p, int* __restrict__ idx, int K, int kkeep)
{
    __shared__ float sp[2048];
    __shared__ int   sidx[2048];
    __shared__ int   sflag[2048];
    int b = blockIdx.x;
    int tid = threadIdx.x;
    for (int j = tid; j < K; j += 256) { sp[j] = p[b*K + j]; sidx[j] = idx[b*Nn + j]; }
    __syncthreads();
    for (int pos = tid; pos < K; pos += 256) {
        float v = sp[pos];
        int r = 0;
        for (int j = 0; j < K; j++) {
            float u = sp[j];
            r += (u > v) || (u == v && j < pos);
        }
        sflag[pos] = (r < kkeep) ? 1 : 0;
    }
    __syncthreads();
    for (int pos = tid; pos < K; pos += 256) {
        if (sflag[pos]) {
            int o = 0;
            for (int j = 0; j < pos; j++) o += sflag[j];
            idx[b*Nn + o] = sidx[pos];
        }
    }
}

// ---------------- host-side pipeline ----------------
static void attn_prop(float* x, const float* s, int l, int K, float* pimp,
                      const float* Wq, const float* bq, const float* Wk, const float* bk,
                      const float* Wv, const float* bv, const float* Wm, const float* bm,
                      const float* W1, const float* b1, const float* W2, const float* b2,
                      float* q, float* k, float* v, float* prob, float* msg, float* y, float* h)
{
    // q/k/v projections
    pw_gemm_kernel<<<dim3(Nn/64, Dm/64, Bsz), 256>>>(Wq + (size_t)l*Dm*Dm, bq + l*Dm,
                                                     x, Dm*Nn, q, Dm*Nn, Dm, Nn, 0);
    pw_gemm_kernel<<<dim3(K/64,  Dm/64, Bsz), 256>>>(Wk + (size_t)l*Dm*Dm, bk + l*Dm,
                                                     s, Dm*K, k, Dm*K, Dm, K, 0);
    pw_gemm_kernel<<<dim3(K/64,  Dm/64, Bsz), 256>>>(Wv + (size_t)l*Dm*Dm, bv + l*Dm,
                                                     s, Dm*K, v, Dm*K, Dm, K, 0);
    // attention
    scores_kernel<<<dim3(K/64, Nn/64, Bsz*Hh), 256>>>(q, k, prob, K);
    softmax_kernel<<<Bsz*Hh*Nn, 256>>>(prob, K);
    zero_kernel<<<(Bsz*K + 255)/256, 256>>>(pimp, Bsz*K);
    pred_kernel<<<dim3((Bsz*K + 255)/256, Nn/128), 256>>>(prob, pimp, K);
    msg_kernel<<<dim3(Nn/64, Bsz*Hh), 256>>>(prob, v, msg, K);
    // concat + message projection into y
    copy_xy_kernel<<<(Bsz*Dm*Nn)/256, 256>>>(x, y);
    pw_gemm_kernel<<<dim3(Nn/64, Dm/64, Bsz), 256>>>(Wm + (size_t)l*Dm*Dm, bm + l*Dm,
                                                     msg, Dm*Nn, y + Dm*Nn, 2*Dm*Nn, Dm, Nn, 0);
    // MLP: h = relu(instnorm(W1 y + b1)); x += W2 h + b2
    pw_gemm_kernel<<<dim3(Nn/64, (2*Dm)/64, Bsz), 256>>>(W1 + (size_t)l*2*Dm*2*Dm, b1 + l*2*Dm,
                                                         y, 2*Dm*Nn, h, 2*Dm*Nn, 2*Dm, Nn, 0);
    instnorm_relu_kernel<<<Bsz*2*Dm, 256>>>(h);
    pw_gemm_kernel<<<dim3(Nn/64, Dm/64, Bsz), 256>>>(W2 + (size_t)l*Dm*2*Dm, b2 + l*Dm,
                                                     h, 2*Dm*Nn, x, Dm*Nn, 2*Dm, Nn, 1);
}

extern "C" void kernel_launch(void* const* d_in, const int* in_sizes, int n_in,
                              void* d_out, int out_size)
{
    const float* x0in = (const float*)d_in[0];
    const float* x1in = (const float*)d_in[1];
    const float* Wq = (const float*)d_in[2];
    const float* bq = (const float*)d_in[3];
    const float* Wk = (const float*)d_in[4];
    const float* bk = (const float*)d_in[5];
    const float* Wv = (const float*)d_in[6];
    const float* bv = (const float*)d_in[7];
    const float* Wm = (const float*)d_in[8];
    const float* bm = (const float*)d_in[9];
    const float* W1 = (const float*)d_in[10];
    const float* b1 = (const float*)d_in[11];
    const float* W2 = (const float*)d_in[12];
    const float* b2 = (const float*)d_in[13];
    float* out = (float*)d_out;

    float *x0, *x1, *s0, *s1, *q, *k, *v, *prob, *msg, *y, *h, *p0, *p1;
    int *idx0, *idx1;
    cudaGetSymbolAddress((void**)&x0, g_x0);
    cudaGetSymbolAddress((void**)&x1, g_x1);
    cudaGetSymbolAddress((void**)&s0, g_s0);
    cudaGetSymbolAddress((void**)&s1, g_s1);
    cudaGetSymbolAddress((void**)&q,  g_q);
    cudaGetSymbolAddress((void**)&k,  g_k);
    cudaGetSymbolAddress((void**)&v,  g_v);
    cudaGetSymbolAddress((void**)&prob, g_prob);
    cudaGetSymbolAddress((void**)&msg,  g_msg);
    cudaGetSymbolAddress((void**)&y,    g_y);
    cudaGetSymbolAddress((void**)&h,    g_h);
    cudaGetSymbolAddress((void**)&p0,   g_p0);
    cudaGetSymbolAddress((void**)&p1,   g_p1);
    cudaGetSymbolAddress((void**)&idx0, g_idx0);
    cudaGetSymbolAddress((void**)&idx1, g_idx1);

    const int total = Bsz*Dm*Nn;
    copyf_kernel<<<total/256, 256>>>(x0in, x0, total);
    copyf_kernel<<<total/256, 256>>>(x1in, x1, total);
    iota_kernel<<<(Bsz*Nn)/256, 256>>>(idx0);
    iota_kernel<<<(Bsz*Nn)/256, 256>>>(idx1);

    const int Ks[4] = {2048, 1024, 512, 256};
    for (int l = 0; l < 4; l++) {
        int K = Ks[l];
        int cross = (l & 1);
        const float* gx0 = cross ? x1 : x0;
        const int*   gi0 = cross ? idx1 : idx0;
        const float* gx1 = cross ? x0 : x1;
        const int*   gi1 = cross ? idx0 : idx1;
        int gth = (Bsz*Dm*K + 255)/256;
        gather_kernel<<<gth, 256>>>(gx0, gi0, s0, K);
        gather_kernel<<<gth, 256>>>(gx1, gi1, s1, K);

        attn_prop(x0, s0, l, K, p0, Wq, bq, Wk, bk, Wv, bv, Wm, bm, W1, b1, W2, b2,
                  q, k, v, prob, msg, y, h);
        attn_prop(x1, s1, l, K, p1, Wq, bq, Wk, bk, Wv, bv, Wm, bm, W1, b1, W2, b2,
                  q, k, v, prob, msg, y, h);

        if (l < 3) {
            int kkeep = K/2;   // always >= MIN_NGHS for this schedule
            if (!cross) {
                pool_kernel<<<Bsz, 256>>>(p0, idx0, K, kkeep);
                pool_kernel<<<Bsz, 256>>>(p1, idx1, K, kkeep);
            } else {
                pool_kernel<<<Bsz, 256>>>(p0, idx1, K, kkeep);
                pool_kernel<<<Bsz, 256>>>(p1, idx0, K, kkeep);
            }
        }
    }

    out_kernel<<<total/256, 256>>>(x0, x1, out);
}

// round 3
// speedup vs baseline: 1.9680x; 1.9680x over previous
#include <cuda_runtime.h>
#include <math.h>

#define Bsz 2
#define Dm  128
#define Nn  2048
#define Hh  4
#define Zs  4
#define ZH  16
typedef unsigned long long u64;

__device__ float g_x [Zs*Dm*Nn];
__device__ float g_s [Zs*Dm*Nn];
__device__ float g_q [Zs*Dm*Nn];
__device__ float g_k [Zs*Dm*Nn];
__device__ float g_v [Zs*Dm*Nn];
__device__ float g_sc[(size_t)ZH*Nn*Nn];
__device__ float g_pm[ZH*16*Nn];
__device__ float g_pz[ZH*16*Nn];
__device__ float g_m [ZH*Nn];
__device__ float g_iz[ZH*Nn];
__device__ float g_msg[Zs*Dm*Nn];
__device__ float g_y [Zs*2*Dm*Nn];
__device__ float g_h [Zs*2*Dm*Nn];
__device__ float g_impp[ZH*16*Nn];
__device__ float g_imp[Zs*Nn];
__device__ int   g_idx[Zs*Nn];

__device__ __forceinline__ u64 ffma2(u64 a, u64 b, u64 c) {
    u64 d; asm("fma.rn.f32x2 %0, %1, %2, %3;" : "=l"(d) : "l"(a), "l"(b), "l"(c)); return d;
}
__device__ __forceinline__ u64 dupf(float x) {
    u64 d; unsigned xi = __float_as_uint(x);
    asm("mov.b64 %0, {%1, %2};" : "=l"(d) : "r"(xi), "r"(xi)); return d;
}
__device__ __forceinline__ float2 unpk(u64 v) {
    unsigned lo, hi; asm("mov.b64 {%0, %1}, %2;" : "=r"(lo), "=r"(hi) : "l"(v));
    return make_float2(__uint_as_float(lo), __uint_as_float(hi));
}

__global__ void copyf4_kernel(const float4* __restrict__ s, float4* __restrict__ d, int n4)
{ int g = blockIdx.x*256 + threadIdx.x; if (g < n4) d[g] = s[g]; }

__global__ void iota_kernel(int* __restrict__ idx)
{ int g = blockIdx.x*256 + threadIdx.x; if (g < Zs*Nn) idx[g] = g % Nn; }

__global__ void copy_xy_kernel(const float4* __restrict__ x, float4* __restrict__ y)
{
    int g = blockIdx.x*256 + threadIdx.x;
    if (g >= Zs*Dm*Nn/4) return;
    int z = g / (Dm*Nn/4), r = g - z*(Dm*Nn/4);
    y[(size_t)z*2*Dm*Nn/4 + r] = x[g];
}

__global__ void gather_kernel(const float* __restrict__ x, const int* __restrict__ idx,
                              float* __restrict__ s, int K, int cross)
{
    int g = blockIdx.x*256 + threadIdx.x;
    if (g >= Zs*Dm*K) return;
    int z = g / (Dm*K), r = g - z*(Dm*K);
    int d = r / K, kk = r - d*K;
    int zs = (((z>>1) ^ cross) << 1) | (z & 1);
    s[g] = x[(size_t)zs*Dm*Nn + (size_t)d*Nn + idx[zs*Nn + kk]];
}

// Y[z,o,n] = sum_i W[o,i] X[z,i,n] + bias[o]; tile 64co x 128n, BK=32
__global__ void __launch_bounds__(256) pw2_kernel(
    const float* __restrict__ W, const float* __restrict__ bias,
    const float* __restrict__ X, int xstr, float* __restrict__ Y, int ystr,
    int Ci, int Ncols, int doacc)
{
    __shared__ float As[32][68];
    __shared__ float Bs[32][132];
    int z = blockIdx.z;
    const float* Xb = X + (size_t)z*xstr;
    float*       Yb = Y + (size_t)z*ystr;
    int co0 = blockIdx.y*64, n0 = blockIdx.x*128;
    int tid = threadIdx.x, ty = tid >> 4, tx = tid & 15;
    u64 c2[4][4];
    #pragma unroll
    for (int i = 0; i < 4; i++) { c2[i][0]=0; c2[i][1]=0; c2[i][2]=0; c2[i][3]=0; }

    for (int kt = 0; kt < Ci; kt += 32) {
        #pragma unroll
        for (int j = 0; j < 2; j++) {
            int e = tid + 256*j, r = e >> 3, kq = e & 7;
            float4 w4 = *(const float4*)&W[(size_t)(co0+r)*Ci + kt + kq*4];
            As[kq*4+0][r]=w4.x; As[kq*4+1][r]=w4.y; As[kq*4+2][r]=w4.z; As[kq*4+3][r]=w4.w;
        }
        #pragma unroll
        for (int j = 0; j < 4; j++) {
            int e = tid + 256*j, kr = e >> 5, c4 = e & 31;
            *(float4*)&Bs[kr][c4*4] = *(const float4*)&Xb[(size_t)(kt+kr)*Ncols + n0 + c4*4];
        }
        __syncthreads();
        #pragma unroll
        for (int kk = 0; kk < 32; kk++) {
            float4 a4 = *(const float4*)&As[kk][ty*4];
            ulonglong2 bA = *(const ulonglong2*)&Bs[kk][tx*8];
            ulonglong2 bB = *(const ulonglong2*)&Bs[kk][tx*8+4];
            float ar[4] = {a4.x, a4.y, a4.z, a4.w};
            #pragma unroll
            for (int r = 0; r < 4; r++) {
                u64 a2 = dupf(ar[r]);
                c2[r][0] = ffma2(a2, bA.x, c2[r][0]);
                c2[r][1] = ffma2(a2, bA.y, c2[r][1]);
                c2[r][2] = ffma2(a2, bB.x, c2[r][2]);
                c2[r][3] = ffma2(a2, bB.y, c2[r][3]);
            }
        }
        __syncthreads();
    }
    #pragma unroll
    for (int r = 0; r < 4; r++) {
        int row = co0 + ty*4 + r;
        float bi = bias[row];
        float2 o0=unpk(c2[r][0]), o1=unpk(c2[r][1]), o2=unpk(c2[r][2]), o3=unpk(c2[r][3]);
        float4 u = make_float4(o0.x+bi, o0.y+bi, o1.x+bi, o1.y+bi);
        float4 w = make_float4(o2.x+bi, o2.y+bi, o3.x+bi, o3.y+bi);
        float* dst = Yb + (size_t)row*Ncols + n0 + tx*8;
        if (doacc) {
            float4 e0 = *(float4*)dst, e1 = *(float4*)(dst+4);
            u.x+=e0.x; u.y+=e0.y; u.z+=e0.z; u.w+=e0.w;
            w.x+=e1.x; w.y+=e1.y; w.z+=e1.z; w.w+=e1.w;
        }
        *(float4*)dst = u; *(float4*)(dst+4) = w;
    }
}

// scores: 128n x 128k tile, dh=32 inner; stores raw scaled scores + partial (max, sumexp)
__global__ void __launch_bounds__(256) scores2_kernel(
    const float* __restrict__ q, const float* __restrict__ kbuf,
    float* __restrict__ sc, float* __restrict__ pm, float* __restrict__ pz, int K)
{
    __shared__ float Qs[32][128];
    __shared__ float Ks[32][128];
    __shared__ float red[128][17];
    __shared__ float rowm[128];
    int zh = blockIdx.z, z = zh >> 2, h = zh & 3;
    int n0 = blockIdx.y*128, k0 = blockIdx.x*128;
    const float* qb = q    + (size_t)z*Dm*Nn;
    const float* kb = kbuf + (size_t)z*Dm*K;
    int tid = threadIdx.x;
    #pragma unroll
    for (int j = 0; j < 4; j++) {
        int e = tid + 256*j, i = e >> 5, c4 = e & 31;
        *(float4*)&Qs[i][c4*4] = *(const float4*)&qb[(size_t)(i*4+h)*Nn + n0 + c4*4];
        *(float4*)&Ks[i][c4*4] = *(const float4*)&kb[(size_t)(i*4+h)*K  + k0 + c4*4];
    }
    __syncthreads();
    int ty = tid >> 4, tx = tid & 15, r0 = ty*8, c0 = tx*8;
    u64 acc[8][4];
    #pragma unroll
    for (int i = 0; i < 8; i++) { acc[i][0]=0; acc[i][1]=0; acc[i][2]=0; acc[i][3]=0; }
    #pragma unroll
    for (int i = 0; i < 32; i++) {
        float4 a0 = *(const float4*)&Qs[i][r0];
        float4 a1 = *(const float4*)&Qs[i][r0+4];
        ulonglong2 bA = *(const ulonglong2*)&Ks[i][c0];
        ulonglong2 bB = *(const ulonglong2*)&Ks[i][c0+4];
        float ar[8] = {a0.x,a0.y,a0.z,a0.w,a1.x,a1.y,a1.z,a1.w};
        #pragma unroll
        for (int r = 0; r < 8; r++) {
            u64 a2 = dupf(ar[r]);
            acc[r][0] = ffma2(a2, bA.x, acc[r][0]);
            acc[r][1] = ffma2(a2, bA.y, acc[r][1]);
            acc[r][2] = ffma2(a2, bB.x, acc[r][2]);
            acc[r][3] = ffma2(a2, bB.y, acc[r][3]);
        }
    }
    const float scale = 0.17677669529663687f;
    float* scb = sc + (size_t)zh*Nn*K;
    float vals[8][8], vmax[8];
    #pragma unroll
    for (int r = 0; r < 8; r++) {
        float2 p0=unpk(acc[r][0]), p1=unpk(acc[r][1]), p2=unpk(acc[r][2]), p3=unpk(acc[r][3]);
        vals[r][0]=p0.x*scale; vals[r][1]=p0.y*scale; vals[r][2]=p1.x*scale; vals[r][3]=p1.y*scale;
        vals[r][4]=p2.x*scale; vals[r][5]=p2.y*scale; vals[r][6]=p3.x*scale; vals[r][7]=p3.y*scale;
        float m = vals[r][0];
        #pragma unroll
        for (int c = 1; c < 8; c++) m = fmaxf(m, vals[r][c]);
        vmax[r] = m;
        float* dst = scb + (size_t)(n0+r0+r)*K + k0 + c0;
        *(float4*)dst     = make_float4(vals[r][0],vals[r][1],vals[r][2],vals[r][3]);
        *(float4*)(dst+4) = make_float4(vals[r][4],vals[r][5],vals[r][6],vals[r][7]);
    }
    #pragma unroll
    for (int r = 0; r < 8; r++) red[r0+r][tx] = vmax[r];
    __syncthreads();
    if (tid < 128) {
        float m = red[tid][0];
        #pragma unroll
        for (int t = 1; t < 16; t++) m = fmaxf(m, red[tid][t]);
        rowm[tid] = m;
    }
    __syncthreads();
    #pragma unroll
    for (int r = 0; r < 8; r++) {
        float m = rowm[r0+r], s = 0.0f;
        #pragma unroll
        for (int c = 0; c < 8; c++) s += expf(vals[r][c] - m);
        red[r0+r][tx] = s;
    }
    __syncthreads();
    if (tid < 128) {
        float s = 0.0f;
        #pragma unroll
        for (int t = 0; t < 16; t++) s += red[tid][t];
        size_t po = ((size_t)zh*gridDim.x + blockIdx.x)*Nn + n0 + tid;
        pm[po] = rowm[tid]; pz[po] = s;
    }
}

__global__ void combine_kernel(const float* __restrict__ pm, const float* __restrict__ pz,
                               float* __restrict__ gm, float* __restrict__ giz, int PT)
{
    int g = blockIdx.x*256 + threadIdx.x;   // ZH*Nn
    int zh = g >> 11, n = g & 2047;
    float m = -1e30f;
    for (int pt = 0; pt < PT; pt++) m = fmaxf(m, pm[((size_t)zh*PT+pt)*Nn + n]);
    float s = 0.0f;
    for (int pt = 0; pt < PT; pt++)
        s += pz[((size_t)zh*PT+pt)*Nn + n] * expf(pm[((size_t)zh*PT+pt)*Nn + n] - m);
    gm[g] = m; giz[g] = 1.0f / s;
}

// msg + importance partials: tile 128n x 32dh, k chunks of 32, prob formed on the fly
__global__ void __launch_bounds__(256) msg2_kernel(
    const float* __restrict__ sc, const float* __restrict__ v,
    const float* __restrict__ gm, const float* __restrict__ giz,
    float* __restrict__ msg, float* __restrict__ impp, int K)
{
    __shared__ float Ps[128][36];
    __shared__ float Vs[32][36];
    __shared__ float mrow[128], izrow[128];
    __shared__ float cred[32][8][4];
    int zh = blockIdx.y, z = zh >> 2, h = zh & 3;
    int n0 = blockIdx.x*128;
    int tid = threadIdx.x;
    const float* scb = sc + (size_t)zh*Nn*K;
    const float* vb  = v  + (size_t)z*Dm*K;
    if (tid < 128) {
        mrow[tid]  = gm [(size_t)zh*Nn + n0 + tid];
        izrow[tid] = giz[(size_t)zh*Nn + n0 + tid];
    }
    __syncthreads();
    int ty = tid >> 3, tx = tid & 7;       // rows ty*4 (128), cols tx*4 (32)
    int rg = tid >> 3, k8 = tid & 7;       // staging: 32 row-groups, 8 k-float4
    u64 c2[4][2];
    #pragma unroll
    for (int i = 0; i < 4; i++) { c2[i][0]=0; c2[i][1]=0; }

    for (int kc = 0; kc < K; kc += 32) {
        float cs0=0.f, cs1=0.f, cs2=0.f, cs3=0.f;
        #pragma unroll
        for (int j = 0; j < 4; j++) {
            int row = rg + 32*j;
            float4 s4 = *(const float4*)&scb[(size_t)(n0+row)*K + kc + k8*4];
            float m = mrow[row], iz = izrow[row];
            float p0 = expf(s4.x-m)*iz, p1 = expf(s4.y-m)*iz;
            float p2 = expf(s4.z-m)*iz, p3 = expf(s4.w-m)*iz;
            *(float4*)&Ps[row][k8*4] = make_float4(p0,p1,p2,p3);
            cs0 += p0; cs1 += p1; cs2 += p2; cs3 += p3;
        }
        cred[rg][k8][0]=cs0; cred[rg][k8][1]=cs1; cred[rg][k8][2]=cs2; cred[rg][k8][3]=cs3;
        {
            int d = tid >> 3, kq = tid & 7;
            float4 v4 = *(const float4*)&vb[(size_t)(d*4+h)*K + kc + kq*4];
            Vs[kq*4+0][d]=v4.x; Vs[kq*4+1][d]=v4.y; Vs[kq*4+2][d]=v4.z; Vs[kq*4+3][d]=v4.w;
        }
        __syncthreads();
        if (tid < 32) {
            float s = 0.0f;
            #pragma unroll
            for (int g2 = 0; g2 < 32; g2++) s += cred[g2][tid>>2][tid&3];
            impp[((size_t)zh*(Nn/128) + blockIdx.x)*K + kc + tid] = s;
        }
        #pragma unroll
        for (int kk = 0; kk < 32; kk++) {
            ulonglong2 b2v = *(const ulonglong2*)&Vs[kk][tx*4];
            #pragma unroll
            for (int r = 0; r < 4; r++) {
                u64 a2 = dupf(Ps[ty*4+r][kk]);
                c2[r][0] = ffma2(a2, b2v.x, c2[r][0]);
                c2[r][1] = ffma2(a2, b2v.y, c2[r][1]);
            }
        }
        __syncthreads();
    }
    float colv[4][4];
    #pragma unroll
    for (int r = 0; r < 4; r++) {
        float2 p0 = unpk(c2[r][0]), p1 = unpk(c2[r][1]);
        colv[0][r]=p0.x; colv[1][r]=p0.y; colv[2][r]=p1.x; colv[3][r]=p1.y;
    }
    #pragma unroll
    for (int cc = 0; cc < 4; cc++) {
        int d = (tx*4 + cc)*4 + h;
        float* dst = msg + (size_t)z*Dm*Nn + (size_t)d*Nn + n0 + ty*4;
        *(float4*)dst = make_float4(colv[cc][0],colv[cc][1],colv[cc][2],colv[cc][3]);
    }
}

__global__ void impreduce_kernel(const float* __restrict__ impp, float* __restrict__ imp, int K)
{
    int g = blockIdx.x*256 + threadIdx.x;
    if (g >= Zs*K) return;
    int z = g / K, k = g - z*K;
    float s = 0.0f;
    for (int h = 0; h < Hh; h++)
        for (int nb = 0; nb < Nn/128; nb++)
            s += impp[((size_t)((z*4+h)*(Nn/128) + nb))*K + k];
    imp[z*Nn + k] = s;
}

__global__ void instnorm_relu_kernel(float* __restrict__ x)
{
    float4* p = (float4*)(x + (size_t)blockIdx.x*Nn);
    int tid = threadIdx.x;
    float4 va = p[tid], vb = p[tid+256];
    float s = va.x+va.y+va.z+va.w + vb.x+vb.y+vb.z+vb.w;
    __shared__ float red[256];
    red[tid] = s; __syncthreads();
    for (int st = 128; st > 0; st >>= 1) { if (tid < st) red[tid] += red[tid+st]; __syncthreads(); }
    float mean = red[0]*(1.0f/Nn);
    __syncthreads();
    float d0=va.x-mean,d1=va.y-mean,d2=va.z-mean,d3=va.w-mean;
    float e0=vb.x-mean,e1=vb.y-mean,e2=vb.z-mean,e3=vb.w-mean;
    red[tid] = d0*d0+d1*d1+d2*d2+d3*d3 + e0*e0+e1*e1+e2*e2+e3*e3;
    __syncthreads();
    for (int st = 128; st > 0; st >>= 1) { if (tid < st) red[tid] += red[tid+st]; __syncthreads(); }
    float rs = rsqrtf(red[0]*(1.0f/Nn) + 1e-3f);
    p[tid]     = make_float4(fmaxf(d0*rs,0.f),fmaxf(d1*rs,0.f),fmaxf(d2*rs,0.f),fmaxf(d3*rs,0.f));
    p[tid+256] = make_float4(fmaxf(e0*rs,0.f),fmaxf(e1*rs,0.f),fmaxf(e2*rs,0.f),fmaxf(e3*rs,0.f));
}

__global__ void pool_kernel(const float* __restrict__ imp, int* __restrict__ idx,
                            int K, int kkeep, int cross)
{
    __shared__ float sp[2048];
    __shared__ int   sidx[2048];
    __shared__ int   sflag[2048];
    int z = blockIdx.x;
    int tz = (((z>>1) ^ cross) << 1) | (z & 1);
    const float* p = imp + (size_t)z*Nn;
    int* ix = idx + (size_t)tz*Nn;
    int tid = threadIdx.x;
    for (int j = tid; j < K; j += 256) { sp[j] = p[j]; sidx[j] = ix[j]; }
    __syncthreads();
    for (int pos = tid; pos < K; pos += 256) {
        float vv = sp[pos];
        int r = 0;
        for (int j = 0; j < K; j++) {
            float u = sp[j];
            r += (u > vv) || (u == vv && j < pos);
        }
        sflag[pos] = (r < kkeep) ? 1 : 0;
    }
    __syncthreads();
    for (int pos = tid; pos < K; pos += 256) {
        if (sflag[pos]) {
            int o = 0;
            for (int j = 0; j < pos; j++) o += sflag[j];
            ix[o] = sidx[pos];
        }
    }
}

extern "C" void kernel_launch(void* const* d_in, const int* in_sizes, int n_in,
                              void* d_out, int out_size)
{
    const float* x0in = (const float*)d_in[0];
    const float* x1in = (const float*)d_in[1];
    const float* Wq = (const float*)d_in[2];  const float* bq = (const float*)d_in[3];
    const float* Wk = (const float*)d_in[4];  const float* bk = (const float*)d_in[5];
    const float* Wv = (const float*)d_in[6];  const float* bv = (const float*)d_in[7];
    const float* Wm = (const float*)d_in[8];  const float* bm = (const float*)d_in[9];
    const float* W1 = (const float*)d_in[10]; const float* b1 = (const float*)d_in[11];
    const float* W2 = (const float*)d_in[12]; const float* b2 = (const float*)d_in[13];
    float* out = (float*)d_out;

    float *x,*s,*q,*k,*v,*sc,*pm,*pz,*m,*iz,*msg,*y,*h,*impp,*imp; int *idx;
    cudaGetSymbolAddress((void**)&x, g_x);   cudaGetSymbolAddress((void**)&s, g_s);
    cudaGetSymbolAddress((void**)&q, g_q);   cudaGetSymbolAddress((void**)&k, g_k);
    cudaGetSymbolAddress((void**)&v, g_v);   cudaGetSymbolAddress((void**)&sc, g_sc);
    cudaGetSymbolAddress((void**)&pm, g_pm); cudaGetSymbolAddress((void**)&pz, g_pz);
    cudaGetSymbolAddress((void**)&m, g_m);   cudaGetSymbolAddress((void**)&iz, g_iz);
    cudaGetSymbolAddress((void**)&msg, g_msg); cudaGetSymbolAddress((void**)&y, g_y);
    cudaGetSymbolAddress((void**)&h, g_h);   cudaGetSymbolAddress((void**)&impp, g_impp);
    cudaGetSymbolAddress((void**)&imp, g_imp); cudaGetSymbolAddress((void**)&idx, g_idx);

    const int DN = Dm*Nn;
    const int n4 = Bsz*DN/4;
    copyf4_kernel<<<(n4+255)/256, 256>>>((const float4*)x0in, (float4*)x, n4);
    copyf4_kernel<<<(n4+255)/256, 256>>>((const float4*)x1in, (float4*)(x + Bsz*DN), n4);
    iota_kernel<<<(Zs*Nn)/256, 256>>>(idx);

    const int Ks[4] = {2048, 1024, 512, 256};
    for (int l = 0; l < 4; l++) {
        int K = Ks[l], cross = (l & 1), DK = Dm*K;

        gather_kernel<<<(Zs*DK)/256, 256>>>(x, idx, s, K, cross);

        pw2_kernel<<<dim3(Nn/128, 2, Zs), 256>>>(Wq+(size_t)l*Dm*Dm, bq+l*Dm, x, DN, q, DN, Dm, Nn, 0);
        pw2_kernel<<<dim3(K/128,  2, Zs), 256>>>(Wk+(size_t)l*Dm*Dm, bk+l*Dm, s, DK, k, DK, Dm, K, 0);
        pw2_kernel<<<dim3(K/128,  2, Zs), 256>>>(Wv+(size_t)l*Dm*Dm, bv+l*Dm, s, DK, v, DK, Dm, K, 0);

        scores2_kernel<<<dim3(K/128, Nn/128, ZH), 256>>>(q, k, sc, pm, pz, K);
        combine_kernel<<<(ZH*Nn)/256, 256>>>(pm, pz, m, iz, K/128);
        msg2_kernel<<<dim3(Nn/128, ZH), 256>>>(sc, v, m, iz, msg, impp, K);
        impreduce_kernel<<<(Zs*K+255)/256, 256>>>(impp, imp, K);

        copy_xy_kernel<<<(Zs*DN/4)/256, 256>>>((const float4*)x, (float4*)y);
        pw2_kernel<<<dim3(Nn/128, 2, Zs), 256>>>(Wm+(size_t)l*Dm*Dm, bm+l*Dm, msg, DN, y+DN, 2*DN, Dm, Nn, 0);
        pw2_kernel<<<dim3(Nn/128, 4, Zs), 256>>>(W1+(size_t)l*2*Dm*2*Dm, b1+l*2*Dm, y, 2*DN, h, 2*DN, 2*Dm, Nn, 0);
        instnorm_relu_kernel<<<Zs*2*Dm, 256>>>(h);
        pw2_kernel<<<dim3(Nn/128, 2, Zs), 256>>>(W2+(size_t)l*Dm*2*Dm, b2+l*Dm, h, 2*DN, x, DN, 2*Dm, Nn, 1);

        if (l < 3)
            pool_kernel<<<Zs, 256>>>(imp, idx, K, K/2, cross);
    }

    copyf4_kernel<<<(Zs*DN/4+255)/256, 256>>>((const float4*)x, (float4*)out, Zs*DN/4);
}

// round 4
// speedup vs baseline: 2.2517x; 1.1441x over previous
#include <cuda_runtime.h>
#include <math.h>

#define Bsz 2
#define Dm  128
#define Nn  2048
#define Hh  4
#define Zs  4
#define ZH  16
typedef unsigned long long u64;

__device__ float g_x [Zs*Dm*Nn];
__device__ float g_s [Zs*Dm*Nn];
__device__ float g_q [Zs*Dm*Nn];
__device__ float g_k [Zs*Dm*Nn];
__device__ float g_v [Zs*Dm*Nn];
__device__ float g_sc[(size_t)ZH*Nn*Nn];
__device__ float g_pm[ZH*16*Nn];
__device__ float g_pz[ZH*16*Nn];
__device__ float g_m [ZH*Nn];
__device__ float g_iz[ZH*Nn];
__device__ float g_msg[Zs*Dm*Nn];
__device__ float g_h [Zs*2*Dm*Nn];
__device__ float g_impp[ZH*8*Nn];
__device__ float g_imp[Zs*Nn];
__device__ int   g_idx[Zs*Nn];
__device__ float g_wc[4*256*128];
__device__ float g_bc[4*256];
__device__ float g_bzero[256];   // zero-initialized

__device__ __forceinline__ u64 ffma2(u64 a, u64 b, u64 c) {
    u64 d; asm("fma.rn.f32x2 %0, %1, %2, %3;" : "=l"(d) : "l"(a), "l"(b), "l"(c)); return d;
}
__device__ __forceinline__ u64 dupf(float x) {
    u64 d; unsigned xi = __float_as_uint(x);
    asm("mov.b64 %0, {%1, %2};" : "=l"(d) : "r"(xi), "r"(xi)); return d;
}
__device__ __forceinline__ float2 unpk(u64 v) {
    unsigned lo, hi; asm("mov.b64 {%0, %1}, %2;" : "=r"(lo), "=r"(hi) : "l"(v));
    return make_float2(__uint_as_float(lo), __uint_as_float(hi));
}

__global__ void copyf4_kernel(const float4* __restrict__ s, float4* __restrict__ d, int n4)
{ int g = blockIdx.x*256 + threadIdx.x; if (g < n4) d[g] = s[g]; }

__global__ void iota_kernel(int* __restrict__ idx)
{ int g = blockIdx.x*256 + threadIdx.x; if (g < Zs*Nn) idx[g] = g % Nn; }

__global__ void gather_kernel(const float* __restrict__ x, const int* __restrict__ idx,
                              float* __restrict__ s, int K, int cross)
{
    int g = blockIdx.x*256 + threadIdx.x;
    if (g >= Zs*Dm*K) return;
    int z = g / (Dm*K), r = g - z*(Dm*K);
    int d = r / K, kk = r - d*K;
    int zs = (((z>>1) ^ cross) << 1) | (z & 1);
    s[g] = x[(size_t)zs*Dm*Nn + (size_t)d*Nn + idx[zs*Nn + kk]];
}

// ---------------- core 128co x 128n GEMM, BK=32, dual-input capable ----------------
__device__ __forceinline__ void pw3_core(
    const float* Wa, int wsa, const float* Xa,
    const float* Wb, int wsb, const float* Xb,
    const float* bias, float* Y,
    int Cia, int Cib, int Ncols, int n0, int co0, int doacc)
{
    __shared__ float As[32][132];
    __shared__ float Bs[32][132];
    int tid = threadIdx.x, ty = tid >> 4, tx = tid & 15;
    u64 acc[8][4];
    #pragma unroll
    for (int i = 0; i < 8; i++) { acc[i][0]=0; acc[i][1]=0; acc[i][2]=0; acc[i][3]=0; }

    int Ct = Cia + Cib;
    for (int kt = 0; kt < Ct; kt += 32) {
        const float* W = (kt < Cia) ? Wa : Wb;
        const float* X = (kt < Cia) ? Xa : Xb;
        int ws = (kt < Cia) ? wsa : wsb;
        int kl = (kt < Cia) ? kt : (kt - Cia);
        #pragma unroll
        for (int j = 0; j < 4; j++) {
            int e = tid + 256*j, r = e >> 3, kq = e & 7;
            float4 w4 = *(const float4*)&W[(size_t)(co0+r)*ws + kl + kq*4];
            As[kq*4+0][r]=w4.x; As[kq*4+1][r]=w4.y; As[kq*4+2][r]=w4.z; As[kq*4+3][r]=w4.w;
        }
        #pragma unroll
        for (int j = 0; j < 4; j++) {
            int e = tid + 256*j, kr = e >> 5, c4 = e & 31;
            *(float4*)&Bs[kr][c4*4] = *(const float4*)&X[(size_t)(kl+kr)*Ncols + n0 + c4*4];
        }
        __syncthreads();
        #pragma unroll
        for (int kk = 0; kk < 32; kk++) {
            float4 a0 = *(const float4*)&As[kk][ty*8];
            float4 a1 = *(const float4*)&As[kk][ty*8+4];
            ulonglong2 bA = *(const ulonglong2*)&Bs[kk][tx*8];
            ulonglong2 bB = *(const ulonglong2*)&Bs[kk][tx*8+4];
            float ar[8] = {a0.x,a0.y,a0.z,a0.w,a1.x,a1.y,a1.z,a1.w};
            #pragma unroll
            for (int r = 0; r < 8; r++) {
                u64 a2 = dupf(ar[r]);
                acc[r][0] = ffma2(a2, bA.x, acc[r][0]);
                acc[r][1] = ffma2(a2, bA.y, acc[r][1]);
                acc[r][2] = ffma2(a2, bB.x, acc[r][2]);
                acc[r][3] = ffma2(a2, bB.y, acc[r][3]);
            }
        }
        __syncthreads();
    }
    #pragma unroll
    for (int r = 0; r < 8; r++) {
        int row = co0 + ty*8 + r;
        float bi = bias[row];
        float2 o0=unpk(acc[r][0]), o1=unpk(acc[r][1]), o2=unpk(acc[r][2]), o3=unpk(acc[r][3]);
        float4 u = make_float4(o0.x+bi, o0.y+bi, o1.x+bi, o1.y+bi);
        float4 w = make_float4(o2.x+bi, o2.y+bi, o3.x+bi, o3.y+bi);
        float* dst = Y + (size_t)row*Ncols + n0 + tx*8;
        if (doacc) {
            float4 e0 = *(float4*)dst, e1 = *(float4*)(dst+4);
            u.x+=e0.x; u.y+=e0.y; u.z+=e0.z; u.w+=e0.w;
            w.x+=e1.x; w.y+=e1.y; w.z+=e1.z; w.w+=e1.w;
        }
        *(float4*)dst = u; *(float4*)(dst+4) = w;
    }
}

// merged q/k/v projection. grid (Nn/128, 1, 12)
__global__ void __launch_bounds__(256) qkv_kernel(
    const float* __restrict__ Wq, const float* __restrict__ bq,
    const float* __restrict__ Wk, const float* __restrict__ bk,
    const float* __restrict__ Wv, const float* __restrict__ bv,
    const float* __restrict__ x, const float* __restrict__ s,
    float* __restrict__ q, float* __restrict__ k, float* __restrict__ v, int K)
{
    int which = blockIdx.z >> 2, z = blockIdx.z & 3;
    int n0 = blockIdx.x*128;
    const float *W, *bias, *X; float* Y; int NC;
    if (which == 0)      { W=Wq; bias=bq; X=x+(size_t)z*Dm*Nn; Y=q+(size_t)z*Dm*Nn; NC=Nn; }
    else if (which == 1) { if (n0 >= K) return; W=Wk; bias=bk; X=s+(size_t)z*Dm*K; Y=k+(size_t)z*Dm*K; NC=K; }
    else                 { if (n0 >= K) return; W=Wv; bias=bv; X=s+(size_t)z*Dm*K; Y=v+(size_t)z*Dm*K; NC=K; }
    pw3_core(W, Dm, X, 0, 0, 0, bias, Y, Dm, 0, NC, n0, 0, 0);
}

// h_pre = W1a@x + Wc@msg + bc.  grid (Nn/128, 2, Zs)
__global__ void __launch_bounds__(256) w1dual_kernel(
    const float* __restrict__ W1, const float* __restrict__ Wc,
    const float* __restrict__ bc,
    const float* __restrict__ x, const float* __restrict__ msg, float* __restrict__ h)
{
    int z = blockIdx.z, co0 = blockIdx.y*128, n0 = blockIdx.x*128;
    pw3_core(W1, 2*Dm, x + (size_t)z*Dm*Nn, Wc, Dm, msg + (size_t)z*Dm*Nn,
             bc, h + (size_t)z*2*Dm*Nn, Dm, Dm, Nn, n0, co0, 0);
}

// Wc[l] = W1b[l] @ Wm[l].  grid (1, 2, 4)
__global__ void __launch_bounds__(256) wc_kernel(
    const float* __restrict__ W1, const float* __restrict__ Wm, float* __restrict__ wc)
{
    int l = blockIdx.z, co0 = blockIdx.y*128;
    pw3_core(W1 + (size_t)l*2*Dm*2*Dm + Dm, 2*Dm, Wm + (size_t)l*Dm*Dm,
             0, 0, 0, g_bzero, wc + (size_t)l*2*Dm*Dm, Dm, 0, Dm, 0, co0, 0);
}

// bc[l] = b1[l] + W1b[l] @ bm[l].  grid 4, 256 threads
__global__ void bc_kernel(const float* __restrict__ W1, const float* __restrict__ bm,
                          const float* __restrict__ b1, float* __restrict__ bc)
{
    int l = blockIdx.x, o = threadIdx.x;
    const float* wrow = W1 + (size_t)l*2*Dm*2*Dm + (size_t)o*2*Dm + Dm;
    const float* bml = bm + l*Dm;
    float s = b1[l*2*Dm + o];
    #pragma unroll 4
    for (int j = 0; j < Dm; j++) s += wrow[j]*bml[j];
    bc[l*2*Dm + o] = s;
}

// legacy 64co x 128n GEMM (used for W2). grid (Ncols/128, Co/64, Zs)
__global__ void __launch_bounds__(256) pw2_kernel(
    const float* __restrict__ W, const float* __restrict__ bias,
    const float* __restrict__ X, int xstr, float* __restrict__ Y, int ystr,
    int Ci, int Ncols, int doacc)
{
    __shared__ float As[32][68];
    __shared__ float Bs[32][132];
    int z = blockIdx.z;
    const float* Xb = X + (size_t)z*xstr;
    float*       Yb = Y + (size_t)z*ystr;
    int co0 = blockIdx.y*64, n0 = blockIdx.x*128;
    int tid = threadIdx.x, ty = tid >> 4, tx = tid & 15;
    u64 c2[4][4];
    #pragma unroll
    for (int i = 0; i < 4; i++) { c2[i][0]=0; c2[i][1]=0; c2[i][2]=0; c2[i][3]=0; }
    for (int kt = 0; kt < Ci; kt += 32) {
        #pragma unroll
        for (int j = 0; j < 2; j++) {
            int e = tid + 256*j, r = e >> 3, kq = e & 7;
            float4 w4 = *(const float4*)&W[(size_t)(co0+r)*Ci + kt + kq*4];
            As[kq*4+0][r]=w4.x; As[kq*4+1][r]=w4.y; As[kq*4+2][r]=w4.z; As[kq*4+3][r]=w4.w;
        }
        #pragma unroll
        for (int j = 0; j < 4; j++) {
            int e = tid + 256*j, kr = e >> 5, c4 = e & 31;
            *(float4*)&Bs[kr][c4*4] = *(const float4*)&Xb[(size_t)(kt+kr)*Ncols + n0 + c4*4];
        }
        __syncthreads();
        #pragma unroll
        for (int kk = 0; kk < 32; kk++) {
            float4 a4 = *(const float4*)&As[kk][ty*4];
            ulonglong2 bA = *(const ulonglong2*)&Bs[kk][tx*8];
            ulonglong2 bB = *(const ulonglong2*)&Bs[kk][tx*8+4];
            float ar[4] = {a4.x, a4.y, a4.z, a4.w};
            #pragma unroll
            for (int r = 0; r < 4; r++) {
                u64 a2 = dupf(ar[r]);
                c2[r][0] = ffma2(a2, bA.x, c2[r][0]);
                c2[r][1] = ffma2(a2, bA.y, c2[r][1]);
                c2[r][2] = ffma2(a2, bB.x, c2[r][2]);
                c2[r][3] = ffma2(a2, bB.y, c2[r][3]);
            }
        }
        __syncthreads();
    }
    #pragma unroll
    for (int r = 0; r < 4; r++) {
        int row = co0 + ty*4 + r;
        float bi = bias[row];
        float2 o0=unpk(c2[r][0]), o1=unpk(c2[r][1]), o2=unpk(c2[r][2]), o3=unpk(c2[r][3]);
        float4 u = make_float4(o0.x+bi, o0.y+bi, o1.x+bi, o1.y+bi);
        float4 w = make_float4(o2.x+bi, o2.y+bi, o3.x+bi, o3.y+bi);
        float* dst = Yb + (size_t)row*Ncols + n0 + tx*8;
        if (doacc) {
            float4 e0 = *(float4*)dst, e1 = *(float4*)(dst+4);
            u.x+=e0.x; u.y+=e0.y; u.z+=e0.z; u.w+=e0.w;
            w.x+=e1.x; w.y+=e1.y; w.z+=e1.z; w.w+=e1.w;
        }
        *(float4*)dst = u; *(float4*)(dst+4) = w;
    }
}

// scores: 128n x 128k tile; raw scaled scores + partial (max, sumexp)
__global__ void __launch_bounds__(256) scores2_kernel(
    const float* __restrict__ q, const float* __restrict__ kbuf,
    float* __restrict__ sc, float* __restrict__ pm, float* __restrict__ pz, int K)
{
    __shared__ float Qs[32][128];
    __shared__ float Ks[32][128];
    __shared__ float red[128][17];
    __shared__ float rowm[128];
    int zh = blockIdx.z, z = zh >> 2, h = zh & 3;
    int n0 = blockIdx.y*128, k0 = blockIdx.x*128;
    const float* qb = q    + (size_t)z*Dm*Nn;
    const float* kb = kbuf + (size_t)z*Dm*K;
    int tid = threadIdx.x;
    #pragma unroll
    for (int j = 0; j < 4; j++) {
        int e = tid + 256*j, i = e >> 5, c4 = e & 31;
        *(float4*)&Qs[i][c4*4] = *(const float4*)&qb[(size_t)(i*4+h)*Nn + n0 + c4*4];
        *(float4*)&Ks[i][c4*4] = *(const float4*)&kb[(size_t)(i*4+h)*K  + k0 + c4*4];
    }
    __syncthreads();
    int ty = tid >> 4, tx = tid & 15, r0 = ty*8, c0 = tx*8;
    u64 acc[8][4];
    #pragma unroll
    for (int i = 0; i < 8; i++) { acc[i][0]=0; acc[i][1]=0; acc[i][2]=0; acc[i][3]=0; }
    #pragma unroll
    for (int i = 0; i < 32; i++) {
        float4 a0 = *(const float4*)&Qs[i][r0];
        float4 a1 = *(const float4*)&Qs[i][r0+4];
        ulonglong2 bA = *(const ulonglong2*)&Ks[i][c0];
        ulonglong2 bB = *(const ulonglong2*)&Ks[i][c0+4];
        float ar[8] = {a0.x,a0.y,a0.z,a0.w,a1.x,a1.y,a1.z,a1.w};
        #pragma unroll
        for (int r = 0; r < 8; r++) {
            u64 a2 = dupf(ar[r]);
            acc[r][0] = ffma2(a2, bA.x, acc[r][0]);
            acc[r][1] = ffma2(a2, bA.y, acc[r][1]);
            acc[r][2] = ffma2(a2, bB.x, acc[r][2]);
            acc[r][3] = ffma2(a2, bB.y, acc[r][3]);
        }
    }
    const float scale = 0.17677669529663687f;
    float* scb = sc + (size_t)zh*Nn*K;
    float vals[8][8], vmax[8];
    #pragma unroll
    for (int r = 0; r < 8; r++) {
        float2 p0=unpk(acc[r][0]), p1=unpk(acc[r][1]), p2=unpk(acc[r][2]), p3=unpk(acc[r][3]);
        vals[r][0]=p0.x*scale; vals[r][1]=p0.y*scale; vals[r][2]=p1.x*scale; vals[r][3]=p1.y*scale;
        vals[r][4]=p2.x*scale; vals[r][5]=p2.y*scale; vals[r][6]=p3.x*scale; vals[r][7]=p3.y*scale;
        float m = vals[r][0];
        #pragma unroll
        for (int c = 1; c < 8; c++) m = fmaxf(m, vals[r][c]);
        vmax[r] = m;
        float* dst = scb + (size_t)(n0+r0+r)*K + k0 + c0;
        *(float4*)dst     = make_float4(vals[r][0],vals[r][1],vals[r][2],vals[r][3]);
        *(float4*)(dst+4) = make_float4(vals[r][4],vals[r][5],vals[r][6],vals[r][7]);
    }
    #pragma unroll
    for (int r = 0; r < 8; r++) red[r0+r][tx] = vmax[r];
    __syncthreads();
    if (tid < 128) {
        float m = red[tid][0];
        #pragma unroll
        for (int t = 1; t < 16; t++) m = fmaxf(m, red[tid][t]);
        rowm[tid] = m;
    }
    __syncthreads();
    #pragma unroll
    for (int r = 0; r < 8; r++) {
        float m = rowm[r0+r], s = 0.0f;
        #pragma unroll
        for (int c = 0; c < 8; c++) s += expf(vals[r][c] - m);
        red[r0+r][tx] = s;
    }
    __syncthreads();
    if (tid < 128) {
        float s = 0.0f;
        #pragma unroll
        for (int t = 0; t < 16; t++) s += red[tid][t];
        size_t po = ((size_t)zh*gridDim.x + blockIdx.x)*Nn + n0 + tid;
        pm[po] = rowm[tid]; pz[po] = s;
    }
}

__global__ void combine_kernel(const float* __restrict__ pm, const float* __restrict__ pz,
                               float* __restrict__ gm, float* __restrict__ giz, int PT)
{
    int g = blockIdx.x*256 + threadIdx.x;
    int zh = g >> 11, n = g & 2047;
    float m = -1e30f;
    for (int pt = 0; pt < PT; pt++) m = fmaxf(m, pm[((size_t)zh*PT+pt)*Nn + n]);
    float s = 0.0f;
    for (int pt = 0; pt < PT; pt++)
        s += pz[((size_t)zh*PT+pt)*Nn + n] * expf(pm[((size_t)zh*PT+pt)*Nn + n] - m);
    gm[g] = m; giz[g] = 1.0f / s;
}

// msg + importance partials: 256n-row blocks, k chunks of 32, thread tile 8n x 4dh
__global__ void __launch_bounds__(256) msg3_kernel(
    const float* __restrict__ sc, const float* __restrict__ v,
    const float* __restrict__ gm, const float* __restrict__ giz,
    float* __restrict__ msg, float* __restrict__ impp, int K)
{
    __shared__ float Ps[256][37];
    __shared__ float Vs[32][36];
    __shared__ float cred[32][8][4];
    int zh = blockIdx.y, z = zh >> 2, h = zh & 3;
    int n0 = blockIdx.x*256;
    int tid = threadIdx.x;
    const float* scb = sc + (size_t)zh*Nn*K;
    const float* vb  = v  + (size_t)z*Dm*K;
    int rg = tid >> 3, k8 = tid & 7;      // staging: rows rg+32j, k-cols k8*4..+3
    float mreg[8], izreg[8];
    #pragma unroll
    for (int j = 0; j < 8; j++) {
        int row = rg + 32*j;
        mreg[j]  = gm [(size_t)zh*Nn + n0 + row];
        izreg[j] = giz[(size_t)zh*Nn + n0 + row];
    }
    u64 c2[8][2];
    #pragma unroll
    for (int i = 0; i < 8; i++) { c2[i][0]=0; c2[i][1]=0; }

    for (int kc = 0; kc < K; kc += 32) {
        float cs0=0.f, cs1=0.f, cs2=0.f, cs3=0.f;
        #pragma unroll
        for (int j = 0; j < 8; j++) {
            int row = rg + 32*j;
            float4 s4 = *(const float4*)&scb[(size_t)(n0+row)*K + kc + k8*4];
            float m = mreg[j], iz = izreg[j];
            float p0 = expf(s4.x-m)*iz, p1 = expf(s4.y-m)*iz;
            float p2 = expf(s4.z-m)*iz, p3 = expf(s4.w-m)*iz;
            Ps[row][k8*4+0]=p0; Ps[row][k8*4+1]=p1; Ps[row][k8*4+2]=p2; Ps[row][k8*4+3]=p3;
            cs0 += p0; cs1 += p1; cs2 += p2; cs3 += p3;
        }
        cred[rg][k8][0]=cs0; cred[rg][k8][1]=cs1; cred[rg][k8][2]=cs2; cred[rg][k8][3]=cs3;
        {
            int d = tid >> 3, kq = tid & 7;
            float4 v4 = *(const float4*)&vb[(size_t)(d*4+h)*K + kc + kq*4];
            Vs[kq*4+0][d]=v4.x; Vs[kq*4+1][d]=v4.y; Vs[kq*4+2][d]=v4.z; Vs[kq*4+3][d]=v4.w;
        }
        __syncthreads();
        if (tid < 32) {
            float s = 0.0f;
            #pragma unroll
            for (int g2 = 0; g2 < 32; g2++) s += cred[g2][tid>>2][tid&3];
            impp[((size_t)zh*(Nn/256) + blockIdx.x)*K + kc + tid] = s;
        }
        int ry = tid >> 3, dx = tid & 7;
        #pragma unroll
        for (int kk = 0; kk < 32; kk++) {
            ulonglong2 bv2 = *(const ulonglong2*)&Vs[kk][dx*4];
            #pragma unroll
            for (int r = 0; r < 8; r++) {
                u64 a2 = dupf(Ps[ry*8+r][kk]);
                c2[r][0] = ffma2(a2, bv2.x, c2[r][0]);
                c2[r][1] = ffma2(a2, bv2.y, c2[r][1]);
            }
        }
        __syncthreads();
    }
    int ry = tid >> 3, dx = tid & 7;
    #pragma unroll
    for (int r = 0; r < 8; r++) {
        float2 p0 = unpk(c2[r][0]), p1 = unpk(c2[r][1]);
        float ov[4] = {p0.x, p0.y, p1.x, p1.y};
        #pragma unroll
        for (int c = 0; c < 4; c++) {
            int d = (dx*4 + c)*4 + h;
            msg[(size_t)z*Dm*Nn + (size_t)d*Nn + n0 + ry*8 + r] = ov[c];
        }
    }
}

__global__ void impreduce_kernel(const float* __restrict__ impp, float* __restrict__ imp, int K)
{
    int g = blockIdx.x*256 + threadIdx.x;
    if (g >= Zs*K) return;
    int z = g / K, k = g - z*K;
    float s = 0.0f;
    for (int h = 0; h < Hh; h++)
        for (int nb = 0; nb < Nn/256; nb++)
            s += impp[((size_t)((z*4+h)*(Nn/256) + nb))*K + k];
    imp[z*Nn + k] = s;
}

__global__ void instnorm_relu_kernel(float* __restrict__ x)
{
    float4* p = (float4*)(x + (size_t)blockIdx.x*Nn);
    int tid = threadIdx.x;
    float4 va = p[tid], vb = p[tid+256];
    float s = va.x+va.y+va.z+va.w + vb.x+vb.y+vb.z+vb.w;
    __shared__ float red[256];
    red[tid] = s; __syncthreads();
    for (int st = 128; st > 0; st >>= 1) { if (tid < st) red[tid] += red[tid+st]; __syncthreads(); }
    float mean = red[0]*(1.0f/Nn);
    __syncthreads();
    float d0=va.x-mean,d1=va.y-mean,d2=va.z-mean,d3=va.w-mean;
    float e0=vb.x-mean,e1=vb.y-mean,e2=vb.z-mean,e3=vb.w-mean;
    red[tid] = d0*d0+d1*d1+d2*d2+d3*d3 + e0*e0+e1*e1+e2*e2+e3*e3;
    __syncthreads();
    for (int st = 128; st > 0; st >>= 1) { if (tid < st) red[tid] += red[tid+st]; __syncthreads(); }
    float rs = rsqrtf(red[0]*(1.0f/Nn) + 1e-3f);
    p[tid]     = make_float4(fmaxf(d0*rs,0.f),fmaxf(d1*rs,0.f),fmaxf(d2*rs,0.f),fmaxf(d3*rs,0.f));
    p[tid+256] = make_float4(fmaxf(e0*rs,0.f),fmaxf(e1*rs,0.f),fmaxf(e2*rs,0.f),fmaxf(e3*rs,0.f));
}

__global__ void pool_kernel(const float* __restrict__ imp, int* __restrict__ idx,
                            int K, int kkeep, int cross)
{
    __shared__ float sp[2048];
    __shared__ int   sidx[2048];
    __shared__ int   sflag[2048];
    int z = blockIdx.x;
    int tz = (((z>>1) ^ cross) << 1) | (z & 1);
    const float* p = imp + (size_t)z*Nn;
    int* ix = idx + (size_t)tz*Nn;
    int tid = threadIdx.x;
    for (int j = tid; j < K; j += 256) { sp[j] = p[j]; sidx[j] = ix[j]; }
    __syncthreads();
    for (int pos = tid; pos < K; pos += 256) {
        float vv = sp[pos];
        int r = 0;
        for (int j = 0; j < K; j++) {
            float u = sp[j];
            r += (u > vv) || (u == vv && j < pos);
        }
        sflag[pos] = (r < kkeep) ? 1 : 0;
    }
    __syncthreads();
    for (int pos = tid; pos < K; pos += 256) {
        if (sflag[pos]) {
            int o = 0;
            for (int j = 0; j < pos; j++) o += sflag[j];
            ix[o] = sidx[pos];
        }
    }
}

extern "C" void kernel_launch(void* const* d_in, const int* in_sizes, int n_in,
                              void* d_out, int out_size)
{
    const float* x0in = (const float*)d_in[0];
    const float* x1in = (const float*)d_in[1];
    const float* Wq = (const float*)d_in[2];  const float* bq = (const float*)d_in[3];
    const float* Wk = (const float*)d_in[4];  const float* bk = (const float*)d_in[5];
    const float* Wv = (const float*)d_in[6];  const float* bv = (const float*)d_in[7];
    const float* Wm = (const float*)d_in[8];  const float* bm = (const float*)d_in[9];
    const float* W1 = (const float*)d_in[10]; const float* b1 = (const float*)d_in[11];
    const float* W2 = (const float*)d_in[12]; const float* b2 = (const float*)d_in[13];
    float* out = (float*)d_out;

    float *x,*s,*q,*k,*v,*sc,*pm,*pz,*m,*iz,*msg,*h,*impp,*imp,*wc,*bc; int *idx;
    cudaGetSymbolAddress((void**)&x, g_x);   cudaGetSymbolAddress((void**)&s, g_s);
    cudaGetSymbolAddress((void**)&q, g_q);   cudaGetSymbolAddress((void**)&k, g_k);
    cudaGetSymbolAddress((void**)&v, g_v);   cudaGetSymbolAddress((void**)&sc, g_sc);
    cudaGetSymbolAddress((void**)&pm, g_pm); cudaGetSymbolAddress((void**)&pz, g_pz);
    cudaGetSymbolAddress((void**)&m, g_m);   cudaGetSymbolAddress((void**)&iz, g_iz);
    cudaGetSymbolAddress((void**)&msg, g_msg);
    cudaGetSymbolAddress((void**)&h, g_h);   cudaGetSymbolAddress((void**)&impp, g_impp);
    cudaGetSymbolAddress((void**)&imp, g_imp); cudaGetSymbolAddress((void**)&idx, g_idx);
    cudaGetSymbolAddress((void**)&wc, g_wc); cudaGetSymbolAddress((void**)&bc, g_bc);

    const int DN = Dm*Nn;
    const int n4 = Bsz*DN/4;
    copyf4_kernel<<<(n4+255)/256, 256>>>((const float4*)x0in, (float4*)x, n4);
    copyf4_kernel<<<(n4+255)/256, 256>>>((const float4*)x1in, (float4*)(x + Bsz*DN), n4);
    iota_kernel<<<(Zs*Nn)/256, 256>>>(idx);
    wc_kernel<<<dim3(1,2,4), 256>>>(W1, Wm, wc);
    bc_kernel<<<4, 256>>>(W1, bm, b1, bc);

    const int Ks[4] = {2048, 1024, 512, 256};
    for (int l = 0; l < 4; l++) {
        int K = Ks[l], cross = (l & 1), DK = Dm*K;

        gather_kernel<<<(Zs*DK)/256, 256>>>(x, idx, s, K, cross);

        qkv_kernel<<<dim3(Nn/128, 1, 12), 256>>>(
            Wq+(size_t)l*Dm*Dm, bq+l*Dm, Wk+(size_t)l*Dm*Dm, bk+l*Dm,
            Wv+(size_t)l*Dm*Dm, bv+l*Dm, x, s, q, k, v, K);

        scores2_kernel<<<dim3(K/128, Nn/128, ZH), 256>>>(q, k, sc, pm, pz, K);
        combine_kernel<<<(ZH*Nn)/256, 256>>>(pm, pz, m, iz, K/128);
        msg3_kernel<<<dim3(Nn/256, ZH), 256>>>(sc, v, m, iz, msg, impp, K);
        impreduce_kernel<<<(Zs*K+255)/256, 256>>>(impp, imp, K);

        w1dual_kernel<<<dim3(Nn/128, 2, Zs), 256>>>(
            W1+(size_t)l*2*Dm*2*Dm, wc+(size_t)l*2*Dm*Dm, bc+l*2*Dm, x, msg, h);
        instnorm_relu_kernel<<<Zs*2*Dm, 256>>>(h);
        pw2_kernel<<<dim3(Nn/128, 2, Zs), 256>>>(W2+(size_t)l*Dm*2*Dm, b2+l*Dm,
                                                 h, 2*DN, x, DN, 2*Dm, Nn, 1);

        if (l < 3)
            pool_kernel<<<Zs, 256>>>(imp, idx, K, K/2, cross);
    }

    copyf4_kernel<<<(Zs*DN/4+255)/256, 256>>>((const float4*)x, (float4*)out, Zs*DN/4);
}